// round 2
// baseline (speedup 1.0000x reference)
#include <cuda_runtime.h>
#include <cstdint>
#include <math.h>

// Problem shape (fixed by the dataset)
constexpr int B_  = 8;
constexpr int N_  = 2048;
constexpr int M_  = 2048;
constexpr int C_  = 512;

// -------- scratch (device-global arrays: allocation-free rule) --------
__device__ float g_S [(size_t)B_ * N_ * M_];   // scores, then probabilities (in-place) ~134MB
__device__ float g_Vt[(size_t)B_ * C_ * M_];   // V transposed per batch [C][M]
__device__ float g_G [(size_t)B_ * N_ * C_];   // gated activations
__device__ float g_H [(size_t)B_ * N_ * C_];   // MLP hidden
__device__ float g_Wt[3 * C_ * C_];            // Wv^T, W1^T, W2^T

// fp32 -> tf32 round-to-nearest via bit trick (hardware ignores low 13 bits)
__device__ __forceinline__ unsigned totf(float f) {
    return __float_as_uint(f) + 0x1000u;
}

// -------- 512x512 transpose --------
__global__ void transpose512(const float* __restrict__ in, float* __restrict__ out) {
    __shared__ float tile[32][33];
    int x = blockIdx.x * 32 + threadIdx.x;
    int y = blockIdx.y * 32 + threadIdx.y;
#pragma unroll
    for (int i = 0; i < 32; i += 8)
        tile[threadIdx.y + i][threadIdx.x] = in[(size_t)(y + i) * C_ + x];
    __syncthreads();
    int x2 = blockIdx.y * 32 + threadIdx.x;
    int y2 = blockIdx.x * 32 + threadIdx.y;
#pragma unroll
    for (int i = 0; i < 32; i += 8)
        out[(size_t)(y2 + i) * C_ + x2] = tile[threadIdx.x][threadIdx.y + i];
}

// -------- NT tf32 GEMM: D[i,j] = sum_k A[i,k]*Bop[j,k]  (+ epilogue) --------
// EPI: 0 = +bias[row]                 (V-transpose build)
//      1 = *extra[idx]                (mask multiply -> scores)
//      2 = extra[idx]*(1+tanh(v))     (tanh-gate with dec)
//      3 = relu(v + bias[col])        (MLP fc1)
//      4 = v + bias[col]              (MLP fc2)
#define MMA_TF32(d, a, b)                                                      \
    asm volatile(                                                              \
        "mma.sync.aligned.m16n8k8.row.col.f32.tf32.tf32.f32 "                  \
        "{%0,%1,%2,%3}, {%4,%5,%6,%7}, {%8,%9}, {%0,%1,%2,%3};\n"              \
        : "+f"(d[0]), "+f"(d[1]), "+f"(d[2]), "+f"(d[3])                       \
        : "r"(a[0]), "r"(a[1]), "r"(a[2]), "r"(a[3]), "r"(b[0]), "r"(b[1]))

template <int EPI>
__global__ __launch_bounds__(256)
void gemm_nt(const float* __restrict__ A, const float* __restrict__ Bop,
             float* __restrict__ D, const float* __restrict__ bias,
             const float* __restrict__ extra,
             int Ncols, int K,
             size_t batA, size_t batB, size_t batD, size_t batE) {
    // blockIdx.y = row tile, blockIdx.x = col tile (x-fastest shares the A tile -> L2 reuse)
    constexpr int LDS_ = 36;  // 32 + 4 pad: fragment loads hit 32 distinct banks
    __shared__ unsigned sA[128 * LDS_];
    __shared__ unsigned sB[128 * LDS_];

    const int tid  = threadIdx.x;
    const int warp = tid >> 5, lane = tid & 31;
    const int wm = warp >> 2, wn = warp & 3;       // 2 x 4 warps, each 64x32
    const int g = lane >> 2, t = lane & 3;

    const float* Ag = A   + (size_t)blockIdx.z * batA + (size_t)blockIdx.y * 128 * K;
    const float* Bg = Bop + (size_t)blockIdx.z * batB + (size_t)blockIdx.x * 128 * K;

    const int lrow = tid >> 3;          // 0..31
    const int lcol = (tid & 7) << 2;    // 0,4,...,28
    float4 ra[4], rb[4];

    auto ldg_tiles = [&](int kb) {
        const float* a0 = Ag + kb * 32 + lcol;
        const float* b0 = Bg + kb * 32 + lcol;
#pragma unroll
        for (int i = 0; i < 4; ++i) {
            ra[i] = *reinterpret_cast<const float4*>(a0 + (size_t)(lrow + 32 * i) * K);
            rb[i] = *reinterpret_cast<const float4*>(b0 + (size_t)(lrow + 32 * i) * K);
        }
    };
    auto sts_tiles = [&]() {
#pragma unroll
        for (int i = 0; i < 4; ++i) {
            unsigned* pa = &sA[(lrow + 32 * i) * LDS_ + lcol];
            pa[0] = totf(ra[i].x); pa[1] = totf(ra[i].y);
            pa[2] = totf(ra[i].z); pa[3] = totf(ra[i].w);
            unsigned* pb = &sB[(lrow + 32 * i) * LDS_ + lcol];
            pb[0] = totf(rb[i].x); pb[1] = totf(rb[i].y);
            pb[2] = totf(rb[i].z); pb[3] = totf(rb[i].w);
        }
    };

    float acc[4][4][4];
#pragma unroll
    for (int a = 0; a < 4; ++a)
#pragma unroll
        for (int b = 0; b < 4; ++b)
#pragma unroll
            for (int r = 0; r < 4; ++r) acc[a][b][r] = 0.f;

    ldg_tiles(0);
    sts_tiles();
    __syncthreads();

    const int nkb = K >> 5;
    for (int kb = 0; kb < nkb; ++kb) {
        if (kb + 1 < nkb) ldg_tiles(kb + 1);
#pragma unroll
        for (int ks = 0; ks < 4; ++ks) {
            unsigned af[4][4], bf[4][2];
            const int kc = ks * 8 + t;
#pragma unroll
            for (int am = 0; am < 4; ++am) {
                const int r0 = (wm * 64 + am * 16 + g) * LDS_ + kc;
                af[am][0] = sA[r0];
                af[am][1] = sA[r0 + 8 * LDS_];
                af[am][2] = sA[r0 + 4];
                af[am][3] = sA[r0 + 8 * LDS_ + 4];
            }
#pragma unroll
            for (int an = 0; an < 4; ++an) {
                const int n0 = (wn * 32 + an * 8 + g) * LDS_ + kc;
                bf[an][0] = sB[n0];
                bf[an][1] = sB[n0 + 4];
            }
#pragma unroll
            for (int am = 0; am < 4; ++am)
#pragma unroll
                for (int an = 0; an < 4; ++an)
                    MMA_TF32(acc[am][an], af[am], bf[an]);
        }
        __syncthreads();
        if (kb + 1 < nkb) { sts_tiles(); __syncthreads(); }
    }

    // epilogue
    const int mbase = blockIdx.y * 128 + wm * 64;
    const int nbase = blockIdx.x * 128 + wn * 32;
    float* Db = D + (size_t)blockIdx.z * batD;
#pragma unroll
    for (int am = 0; am < 4; ++am)
#pragma unroll
        for (int an = 0; an < 4; ++an)
#pragma unroll
            for (int r = 0; r < 4; ++r) {
                const int row = mbase + am * 16 + g + ((r & 2) ? 8 : 0);
                const int col = nbase + an * 8 + t * 2 + (r & 1);
                const size_t idx = (size_t)row * Ncols + col;
                float v = acc[am][an][r];
                if constexpr (EPI == 0) {
                    Db[idx] = v + bias[row];
                } else if constexpr (EPI == 1) {
                    const float* Eb = extra + (size_t)blockIdx.z * batE;
                    Db[idx] = v * Eb[idx];
                } else if constexpr (EPI == 2) {
                    const float* Eb = extra + (size_t)blockIdx.z * batE;
                    Db[idx] = Eb[idx] * (1.0f + tanhf(v));
                } else if constexpr (EPI == 3) {
                    Db[idx] = fmaxf(v + bias[col], 0.0f);
                } else {
                    Db[idx] = v + bias[col];
                }
            }
}

// -------- nonstandard masked softmax, in place, one CTA per row --------
// max over ALL entries (zeros included); denom includes exp(0-max) for masked
// entries; positions whose stored value is exactly 0 are re-zeroed.
__global__ void softmax_k(float* __restrict__ S) {
    __shared__ float sh[8];
    const int tid = threadIdx.x;
    float* p = S + (size_t)blockIdx.x * M_;

    float mx = -3.402823466e38f;
    for (int i = tid; i < M_; i += 256) mx = fmaxf(mx, p[i]);
#pragma unroll
    for (int o = 16; o > 0; o >>= 1) mx = fmaxf(mx, __shfl_xor_sync(0xffffffffu, mx, o));
    if ((tid & 31) == 0) sh[tid >> 5] = mx;
    __syncthreads();
    if (tid == 0) {
        float m = sh[0];
        for (int j = 1; j < 8; ++j) m = fmaxf(m, sh[j]);
        sh[0] = m;
    }
    __syncthreads();
    mx = sh[0];
    __syncthreads();

    float s = 0.f;
    for (int i = tid; i < M_; i += 256) s += expf(p[i] - mx);
#pragma unroll
    for (int o = 16; o > 0; o >>= 1) s += __shfl_xor_sync(0xffffffffu, s, o);
    if ((tid & 31) == 0) sh[tid >> 5] = s;
    __syncthreads();
    if (tid == 0) {
        float tot = 0.f;
        for (int j = 0; j < 8; ++j) tot += sh[j];
        sh[0] = tot;
    }
    __syncthreads();
    const float inv = 1.0f / sh[0];

    for (int i = tid; i < M_; i += 256) {
        const float v = p[i];
        p[i] = (v != 0.0f) ? expf(v - mx) * inv : 0.0f;
    }
}

extern "C" void kernel_launch(void* const* d_in, const int* in_sizes, int n_in,
                              void* d_out, int out_size) {
    (void)in_sizes; (void)n_in; (void)out_size;
    const float* dec   = (const float*)d_in[0];
    const float* enc   = (const float*)d_in[1];
    const float* trans = (const float*)d_in[2];
    const float* Wv    = (const float*)d_in[3];
    const float* bv    = (const float*)d_in[4];
    const float* W1    = (const float*)d_in[5];
    const float* b1    = (const float*)d_in[6];
    const float* W2    = (const float*)d_in[7];
    const float* b2    = (const float*)d_in[8];
    float* out = (float*)d_out;

    float *S, *Vt, *G, *H, *Wt;
    cudaGetSymbolAddress((void**)&S,  g_S);
    cudaGetSymbolAddress((void**)&Vt, g_Vt);
    cudaGetSymbolAddress((void**)&G,  g_G);
    cudaGetSymbolAddress((void**)&H,  g_H);
    cudaGetSymbolAddress((void**)&Wt, g_Wt);
    float* Wvt = Wt;
    float* W1t = Wt + (size_t)C_ * C_;
    float* W2t = Wt + 2 * (size_t)C_ * C_;

    const size_t NC = (size_t)N_ * C_;
    const size_t MC = (size_t)M_ * C_;
    const size_t NM = (size_t)N_ * M_;
    const size_t CM = (size_t)C_ * M_;

    dim3 tb(32, 8), tg(C_ / 32, C_ / 32);
    transpose512<<<tg, tb>>>(Wv, Wvt);
    transpose512<<<tg, tb>>>(W1, W1t);
    transpose512<<<tg, tb>>>(W2, W2t);

    // Vt[b][c][m] = sum_k Wv[k,c]*enc[b,m,k] + bv[c]   (rows = C -> coalesced)
    gemm_nt<0><<<dim3(M_ / 128, C_ / 128, B_), 256>>>(
        Wvt, enc, Vt, bv, nullptr, M_, C_, 0, MC, CM, 0);

    // S[b,n,m] = (dec[b,n,:] . enc[b,m,:]) * trans[b,n,m]
    gemm_nt<1><<<dim3(M_ / 128, N_ / 128, B_), 256>>>(
        dec, enc, S, nullptr, trans, M_, C_, NC, MC, NM, NM);

    // in-place masked softmax over m
    softmax_k<<<B_ * N_, 256>>>(S);

    // G[b,n,c] = dec[b,n,c] * (1 + tanh(sum_m P[b,n,m]*Vt[b][c][m]))
    gemm_nt<2><<<dim3(C_ / 128, N_ / 128, B_), 256>>>(
        S, Vt, G, nullptr, dec, C_, M_, NM, CM, NC, NC);

    // H = relu(G @ W1 + b1)  (flattened over batch)
    gemm_nt<3><<<dim3(C_ / 128, (B_ * N_) / 128, 1), 256>>>(
        G, W1t, H, b1, nullptr, C_, C_, 0, 0, 0, 0);

    // out = H @ W2 + b2
    gemm_nt<4><<<dim3(C_ / 128, (B_ * N_) / 128, 1), 256>>>(
        H, W2t, out, b2, nullptr, C_, C_, 0, 0, 0, 0);
}

// round 3
// speedup vs baseline: 1.3449x; 1.3449x over previous
#include <cuda_runtime.h>
#include <cstdint>
#include <math.h>

// Problem shape (fixed by the dataset)
constexpr int B_  = 8;
constexpr int N_  = 2048;
constexpr int M_  = 2048;
constexpr int C_  = 512;

// -------- scratch (device-global arrays: allocation-free rule) --------
__device__ float g_S [(size_t)B_ * N_ * M_];   // scores, then probabilities (in-place)
__device__ float g_Vt[(size_t)B_ * C_ * M_];   // V transposed per batch [C][M] (tf32-rounded)
__device__ float g_G [(size_t)B_ * N_ * C_];   // gated activations (tf32-rounded)
__device__ float g_H [(size_t)B_ * N_ * C_];   // MLP hidden (tf32-rounded)
__device__ float g_Wt[3 * C_ * C_];            // Wv^T, W1^T, W2^T (tf32-rounded)
__device__ float g_Dr[(size_t)B_ * N_ * C_];   // dec, tf32-rounded
__device__ float g_Er[(size_t)B_ * M_ * C_];   // enc, tf32-rounded

// round fp32 to tf32-RN (HW truncation of low 13 bits completes the rounding)
__device__ __forceinline__ float rnd(float f) {
    return __uint_as_float(__float_as_uint(f) + 0x1000u);
}

__device__ __forceinline__ void cp16(void* smem, const void* gmem) {
    unsigned sa = (unsigned)__cvta_generic_to_shared(smem);
    asm volatile("cp.async.cg.shared.global [%0], [%1], 16;\n" :: "r"(sa), "l"(gmem));
}
#define CP_COMMIT() asm volatile("cp.async.commit_group;\n")
#define CP_WAIT1()  asm volatile("cp.async.wait_group 1;\n")

// -------- elementwise tf32 rounding copy --------
__global__ void round_copy4(const float4* __restrict__ in, float4* __restrict__ out, int n4) {
    int i = blockIdx.x * 256 + threadIdx.x;
    if (i < n4) {
        float4 v = in[i];
        v.x = rnd(v.x); v.y = rnd(v.y); v.z = rnd(v.z); v.w = rnd(v.w);
        out[i] = v;
    }
}

// -------- 512x512 transpose (+tf32 rounding) --------
__global__ void transpose512(const float* __restrict__ in, float* __restrict__ out) {
    __shared__ float tile[32][33];
    int x = blockIdx.x * 32 + threadIdx.x;
    int y = blockIdx.y * 32 + threadIdx.y;
#pragma unroll
    for (int i = 0; i < 32; i += 8)
        tile[threadIdx.y + i][threadIdx.x] = in[(size_t)(y + i) * C_ + x];
    __syncthreads();
    int x2 = blockIdx.y * 32 + threadIdx.x;
    int y2 = blockIdx.x * 32 + threadIdx.y;
#pragma unroll
    for (int i = 0; i < 32; i += 8)
        out[(size_t)(y2 + i) * C_ + x2] = rnd(tile[threadIdx.x][threadIdx.y + i]);
}

// -------- NT tf32 GEMM (cp.async 3-stage, XOR swizzle): D[i,j]=sum_k A[i,k]*B[j,k] --------
// EPI: 0 = rnd(v+bias[row])            (Vt build)
//      1 = v*extra[idx]                (mask-mul -> scores; NOT rounded, feeds softmax)
//      2 = rnd(extra[idx]*(1+tanh(v))) (tanh-gate with full-precision dec)
//      3 = rnd(relu(v+bias[col]))      (fc1)
//      4 = v+bias[col]                 (fc2, exact final output)
#define MMA_TF32(d, a, b)                                                      \
    asm volatile(                                                              \
        "mma.sync.aligned.m16n8k8.row.col.f32.tf32.tf32.f32 "                  \
        "{%0,%1,%2,%3}, {%4,%5,%6,%7}, {%8,%9}, {%0,%1,%2,%3};\n"              \
        : "+f"(d[0]), "+f"(d[1]), "+f"(d[2]), "+f"(d[3])                       \
        : "r"(a[0]), "r"(a[1]), "r"(a[2]), "r"(a[3]), "r"(b[0]), "r"(b[1]))

constexpr int STAGES = 3;
constexpr int STAGE_F = 2 * 128 * 32;              // floats per stage (sA+sB)
constexpr int GEMM_SMEM = STAGES * STAGE_F * 4;    // 96 KB

template <int EPI>
__global__ __launch_bounds__(256, 2)
void gemm_nt(const float* __restrict__ A, const float* __restrict__ Bop,
             float* __restrict__ D, const float* __restrict__ bias,
             const float* __restrict__ extra,
             int Ncols, int K,
             size_t batA, size_t batB, size_t batD, size_t batE) {
    extern __shared__ float smem[];

    const int tid  = threadIdx.x;
    const int warp = tid >> 5, lane = tid & 31;
    const int wm = warp >> 2, wn = warp & 3;       // 2 x 4 warps, each 64x32
    const int g = lane >> 2, t = lane & 3;

    const float* Ag = A   + (size_t)blockIdx.z * batA + (size_t)blockIdx.y * 128 * K;
    const float* Bg = Bop + (size_t)blockIdx.z * batB + (size_t)blockIdx.x * 128 * K;

    const int lrow = tid >> 3;           // 0..31
    const int lcol = (tid & 7) << 2;     // 0,4,...,28
    const int swz  = lcol ^ ((lrow & 7) << 2);   // (lrow+32i)&7 == lrow&7

    auto issue = [&](int kb, int stg) {
        float* sA = smem + stg * STAGE_F;
        float* sB = sA + 128 * 32;
        const float* a0 = Ag + kb * 32 + lcol;
        const float* b0 = Bg + kb * 32 + lcol;
#pragma unroll
        for (int i = 0; i < 4; ++i) {
            const int r = lrow + 32 * i;
            cp16(&sA[r * 32 + swz], a0 + (size_t)r * K);
            cp16(&sB[r * 32 + swz], b0 + (size_t)r * K);
        }
    };

    float acc[4][4][4];
#pragma unroll
    for (int a = 0; a < 4; ++a)
#pragma unroll
        for (int b = 0; b < 4; ++b)
#pragma unroll
            for (int r = 0; r < 4; ++r) acc[a][b][r] = 0.f;

    const int nkb = K >> 5;              // >= 16 always
    issue(0, 0); CP_COMMIT();
    issue(1, 1); CP_COMMIT();

    for (int kb = 0; kb < nkb; ++kb) {
        CP_WAIT1();                      // stage kb complete (this thread's part)
        __syncthreads();                 // all threads' stage-kb copies visible
        if (kb + 2 < nkb) issue(kb + 2, (kb + 2) % STAGES);
        CP_COMMIT();                     // always commit (possibly empty group)

        const float* sA = smem + (kb % STAGES) * STAGE_F;
        const float* sB = sA + 128 * 32;
        const int sw = g << 2;

#pragma unroll
        for (int ks = 0; ks < 4; ++ks) {
            const int kc = ks * 8 + t;
            const int c0 = kc ^ sw, c1 = (kc + 4) ^ sw;
            unsigned af[4][4], bf[4][2];
#pragma unroll
            for (int am = 0; am < 4; ++am) {
                const float* base = sA + (wm * 64 + am * 16 + g) * 32;
                af[am][0] = __float_as_uint(base[c0]);
                af[am][1] = __float_as_uint(base[8 * 32 + c0]);
                af[am][2] = __float_as_uint(base[c1]);
                af[am][3] = __float_as_uint(base[8 * 32 + c1]);
            }
#pragma unroll
            for (int an = 0; an < 4; ++an) {
                const float* nb = sB + (wn * 32 + an * 8 + g) * 32;
                bf[an][0] = __float_as_uint(nb[c0]);
                bf[an][1] = __float_as_uint(nb[c1]);
            }
#pragma unroll
            for (int am = 0; am < 4; ++am)
#pragma unroll
                for (int an = 0; an < 4; ++an)
                    MMA_TF32(acc[am][an], af[am], bf[an]);
        }
    }

    // epilogue
    const int mbase = blockIdx.y * 128 + wm * 64;
    const int nbase = blockIdx.x * 128 + wn * 32;
    float* Db = D + (size_t)blockIdx.z * batD;
#pragma unroll
    for (int am = 0; am < 4; ++am)
#pragma unroll
        for (int an = 0; an < 4; ++an)
#pragma unroll
            for (int r = 0; r < 4; ++r) {
                const int row = mbase + am * 16 + g + ((r & 2) ? 8 : 0);
                const int col = nbase + an * 8 + t * 2 + (r & 1);
                const size_t idx = (size_t)row * Ncols + col;
                float v = acc[am][an][r];
                if constexpr (EPI == 0) {
                    Db[idx] = rnd(v + bias[row]);
                } else if constexpr (EPI == 1) {
                    const float* Eb = extra + (size_t)blockIdx.z * batE;
                    Db[idx] = v * Eb[idx];                 // exact; feeds softmax
                } else if constexpr (EPI == 2) {
                    const float* Eb = extra + (size_t)blockIdx.z * batE;
                    Db[idx] = rnd(Eb[idx] * (1.0f + tanhf(v)));
                } else if constexpr (EPI == 3) {
                    Db[idx] = rnd(fmaxf(v + bias[col], 0.0f));
                } else {
                    Db[idx] = v + bias[col];               // exact final output
                }
            }
}

// -------- nonstandard masked softmax, in place, one CTA per row (smem-cached) --------
// max over ALL entries (zeros included); denom includes exp(0-max) for masked
// entries; positions whose stored value is exactly 0 stay 0. Output tf32-rounded
// (feeds the PV MMA).
__global__ __launch_bounds__(256)
void softmax_k(float* __restrict__ S) {
    __shared__ float row[M_];
    __shared__ float red[8];
    const int tid = threadIdx.x;
    float4* p4 = reinterpret_cast<float4*>(S + (size_t)blockIdx.x * M_);

    float mx = -3.402823466e38f;
    float4 v[2];
#pragma unroll
    for (int j = 0; j < 2; ++j) {
        const int i = tid + j * 256;
        v[j] = p4[i];
        reinterpret_cast<float4*>(row)[i] = v[j];
        mx = fmaxf(mx, fmaxf(fmaxf(v[j].x, v[j].y), fmaxf(v[j].z, v[j].w)));
    }
#pragma unroll
    for (int o = 16; o > 0; o >>= 1) mx = fmaxf(mx, __shfl_xor_sync(0xffffffffu, mx, o));
    if ((tid & 31) == 0) red[tid >> 5] = mx;
    __syncthreads();
    if (tid == 0) {
        float m = red[0];
#pragma unroll
        for (int j = 1; j < 8; ++j) m = fmaxf(m, red[j]);
        red[0] = m;
    }
    __syncthreads();
    mx = red[0];
    __syncthreads();

    float s = 0.f;
#pragma unroll
    for (int j = 0; j < 2; ++j) {
        s += expf(v[j].x - mx) + expf(v[j].y - mx) + expf(v[j].z - mx) + expf(v[j].w - mx);
    }
#pragma unroll
    for (int o = 16; o > 0; o >>= 1) s += __shfl_xor_sync(0xffffffffu, s, o);
    if ((tid & 31) == 0) red[tid >> 5] = s;
    __syncthreads();
    if (tid == 0) {
        float tot = 0.f;
#pragma unroll
        for (int j = 0; j < 8; ++j) tot += red[j];
        red[0] = tot;
    }
    __syncthreads();
    const float inv = 1.0f / red[0];

#pragma unroll
    for (int j = 0; j < 2; ++j) {
        const int i = tid + j * 256;
        float4 w = v[j];
        w.x = (w.x != 0.0f) ? rnd(expf(w.x - mx) * inv) : 0.0f;
        w.y = (w.y != 0.0f) ? rnd(expf(w.y - mx) * inv) : 0.0f;
        w.z = (w.z != 0.0f) ? rnd(expf(w.z - mx) * inv) : 0.0f;
        w.w = (w.w != 0.0f) ? rnd(expf(w.w - mx) * inv) : 0.0f;
        p4[i] = w;
    }
}

template <int EPI>
static void launch_gemm(dim3 grid, const float* A, const float* Bop, float* D,
                        const float* bias, const float* extra,
                        int Ncols, int K, size_t batA, size_t batB, size_t batD, size_t batE) {
    static bool attr_done = false;
    if (!attr_done) {
        cudaFuncSetAttribute(gemm_nt<EPI>, cudaFuncAttributeMaxDynamicSharedMemorySize, GEMM_SMEM);
        attr_done = true;
    }
    gemm_nt<EPI><<<grid, 256, GEMM_SMEM>>>(A, Bop, D, bias, extra, Ncols, K, batA, batB, batD, batE);
}

extern "C" void kernel_launch(void* const* d_in, const int* in_sizes, int n_in,
                              void* d_out, int out_size) {
    (void)in_sizes; (void)n_in; (void)out_size;
    const float* dec   = (const float*)d_in[0];
    const float* enc   = (const float*)d_in[1];
    const float* trans = (const float*)d_in[2];
    const float* Wv    = (const float*)d_in[3];
    const float* bv    = (const float*)d_in[4];
    const float* W1    = (const float*)d_in[5];
    const float* b1    = (const float*)d_in[6];
    const float* W2    = (const float*)d_in[7];
    const float* b2    = (const float*)d_in[8];
    float* out = (float*)d_out;

    float *S, *Vt, *G, *H, *Wt, *Dr, *Er;
    cudaGetSymbolAddress((void**)&S,  g_S);
    cudaGetSymbolAddress((void**)&Vt, g_Vt);
    cudaGetSymbolAddress((void**)&G,  g_G);
    cudaGetSymbolAddress((void**)&H,  g_H);
    cudaGetSymbolAddress((void**)&Wt, g_Wt);
    cudaGetSymbolAddress((void**)&Dr, g_Dr);
    cudaGetSymbolAddress((void**)&Er, g_Er);
    float* Wvt = Wt;
    float* W1t = Wt + (size_t)C_ * C_;
    float* W2t = Wt + 2 * (size_t)C_ * C_;

    const size_t NC = (size_t)N_ * C_;
    const size_t MC = (size_t)M_ * C_;
    const size_t NM = (size_t)N_ * M_;
    const size_t CM = (size_t)C_ * M_;

    // pre-round inputs to tf32 so cp.async tiles need no conversion pass
    const int n4 = (int)(NC * B_ / 4);
    round_copy4<<<(n4 + 255) / 256, 256>>>((const float4*)dec, (float4*)Dr, n4);
    round_copy4<<<(n4 + 255) / 256, 256>>>((const float4*)enc, (float4*)Er, n4);

    dim3 tb(32, 8), tg(C_ / 32, C_ / 32);
    transpose512<<<tg, tb>>>(Wv, Wvt);
    transpose512<<<tg, tb>>>(W1, W1t);
    transpose512<<<tg, tb>>>(W2, W2t);

    // Vt[b][c][m] = sum_k Wv[k,c]*enc[b,m,k] + bv[c]
    launch_gemm<0>(dim3(M_ / 128, C_ / 128, B_), Wvt, Er, Vt, bv, nullptr, M_, C_, 0, MC, CM, 0);

    // S[b,n,m] = (dec[b,n,:] . enc[b,m,:]) * trans[b,n,m]
    launch_gemm<1>(dim3(M_ / 128, N_ / 128, B_), Dr, Er, S, nullptr, trans, M_, C_, NC, MC, NM, NM);

    // in-place masked softmax over m (writes tf32-rounded P)
    softmax_k<<<B_ * N_, 256>>>(S);

    // G[b,n,c] = dec[b,n,c] * (1 + tanh(sum_m P[b,n,m]*Vt[b][c][m]))
    launch_gemm<2>(dim3(C_ / 128, N_ / 128, B_), S, Vt, G, nullptr, dec, C_, M_, NM, CM, NC, NC);

    // H = relu(G @ W1 + b1)
    launch_gemm<3>(dim3(C_ / 128, (B_ * N_) / 128, 1), G, W1t, H, b1, nullptr, C_, C_, 0, 0, 0, 0);

    // out = H @ W2 + b2
    launch_gemm<4>(dim3(C_ / 128, (B_ * N_) / 128, 1), H, W2t, out, b2, nullptr, C_, C_, 0, 0, 0, 0);
}